// round 10
// baseline (speedup 1.0000x reference)
#include <cuda_runtime.h>
#include <cuda_bf16.h>
#include <cuda_fp16.h>

// Problem constants
#define BB   512
#define SS   1024
#define SSP  (SS + 2)  // padded rows per batch (prefetch overrun)
#define FIN  16        // features per (b,s); feature 15 is delta
#define HH   64
#define GG   192       // 3*H
#define NBC  2         // batches per scan CTA (warps 0,1 -> u0; 2,3 -> u1)
#define XROWS 64       // rows per x-projection block
#define NTP  192       // x-projection block threads

typedef unsigned long long u64;

// Device scratch (sanctioned alternative to cudaMalloc)
__device__ __half g_xp[(size_t)BB * SSP * GG];   // x-projection + folded biases (fp16, ~202 MB)

// ---- packed f32x2 helpers (bit-exact fp32, 2 FMA per fma-pipe slot) ----
__device__ __forceinline__ u64 pack2(float lo, float hi) {
    u64 r; asm("mov.b64 %0, {%1, %2};" : "=l"(r) : "f"(lo), "f"(hi)); return r;
}
__device__ __forceinline__ void unpack2(u64 v, float& lo, float& hi) {
    asm("mov.b64 {%0, %1}, %2;" : "=f"(lo), "=f"(hi) : "l"(v));
}
__device__ __forceinline__ u64 fma2(u64 a, u64 b, u64 c) {
    u64 d; asm("fma.rn.f32x2 %0, %1, %2, %3;" : "=l"(d) : "l"(a), "l"(b), "l"(c)); return d;
}
__device__ __forceinline__ u64 add2(u64 a, u64 b) {
    u64 d; asm("add.rn.f32x2 %0, %1, %2;" : "=l"(d) : "l"(a), "l"(b)); return d;
}
__device__ __forceinline__ float tanh_fast(float x) {
    float t; asm("tanh.approx.f32 %0, %1;" : "=f"(t) : "f"(x)); return t;
}

// ---------------- Kernel 1: x-projection pre-pass (fp16 out, biases folded) ----------------
// For g<128 (z,r gates): xp = x.K + b_in[g] + b_rec[g]
// For g>=128 (h gate):   xp = x.K + b_in[g]            (b_rec stays in scan)
__global__ __launch_bounds__(NTP)
void xproj_kernel(const float* __restrict__ inputs,
                  const float* __restrict__ k_in,
                  const float* __restrict__ bias) {
    __shared__ __align__(16) float sx[XROWS * FIN];
    const int g  = threadIdx.x;
    const int bb = blockIdx.x / (SS / XROWS);        // batch
    const int s0 = (blockIdx.x % (SS / XROWS)) * XROWS;
    const size_t row0 = (size_t)bb * SS + s0;        // source row
    const size_t drow0 = (size_t)bb * SSP + s0;      // dest row (padded layout)

    u64 K2[8];
    #pragma unroll
    for (int f2 = 0; f2 < 8; f2++) {
        float lo = k_in[(2 * f2) * GG + g];
        float hi = (2 * f2 + 1 < 15) ? k_in[(2 * f2 + 1) * GG + g] : 0.0f;
        K2[f2] = pack2(lo, hi);
    }
    const float bfold = bias[g] + ((g < 128) ? bias[GG + g] : 0.0f);

    const float4* src = (const float4*)(inputs + row0 * FIN);
    for (int i = g; i < XROWS * 4; i += NTP) ((float4*)sx)[i] = src[i];
    __syncthreads();

    __half* dst = g_xp + drow0 * GG + g;
    #pragma unroll 4
    for (int r = 0; r < XROWS; r++) {
        const ulonglong2* xr = (const ulonglong2*)(sx + r * FIN);
        ulonglong2 xv0 = xr[0], xv1 = xr[1];
        u64 c0 = fma2(xv0.x, K2[0], 0ull);
        u64 c1 = fma2(xv0.y, K2[1], 0ull);
        c0 = fma2(xv1.x, K2[2], c0);
        c1 = fma2(xv1.y, K2[3], c1);
        ulonglong2 xv2 = xr[2], xv3 = xr[3];
        c0 = fma2(xv2.x, K2[4], c0);
        c1 = fma2(xv2.y, K2[5], c1);
        c0 = fma2(xv3.x, K2[6], c0);
        c1 = fma2(xv3.y, K2[7], c1);
        float lo, hi; unpack2(add2(c0, c1), lo, hi);
        dst[(size_t)r * GG] = __float2half(bfold + (lo + hi));
    }
}

// ---------------- Kernel 2: GRU scan — 2 batches/CTA, thread = column triple ----------------
__global__ __launch_bounds__(NBC * HH, 2)
void gru_scan_kernel(const float* __restrict__ inputs,   // (B,S,16) - for delta mean
                     const float* __restrict__ r_in,     // (64,192)
                     const float* __restrict__ bias,     // (2,192)
                     const float* __restrict__ w1,       // (64,64)
                     const float* __restrict__ b1,       // (64)
                     const float* __restrict__ bn_gamma,
                     const float* __restrict__ bn_beta,
                     const float* __restrict__ bn_mean,
                     const float* __restrict__ bn_var,
                     const float* __restrict__ w2,       // (64,1)
                     const float* __restrict__ b2,       // (1)
                     const float* __restrict__ Tp,       // (1)
                     float* __restrict__ out)            // (B,1)
{
    __shared__ __align__(16) float sm_h[2][NBC][HH];   // double-buffered hidden state per batch
    __shared__ float sm_e[NBC][HH];
    __shared__ float sm_r[NBC][HH];

    const int tid = threadIdx.x;
    const int j = tid & 63;               // column triple 0..63
    const int u = tid >> 6;               // batch slot within CTA (warps 0,1 -> 0 ; 2,3 -> 1)
    const int b = blockIdx.x * NBC + u;   // batch

    // Recurrent weights for columns j (z), 64+j (r), 128+j (h); f32x2 pairs over k
    u64 Rz[32], Rr[32], Rh[32];
    #pragma unroll
    for (int k2 = 0; k2 < 32; k2++) {
        Rz[k2] = pack2(r_in[(2 * k2) * GG + j],        r_in[(2 * k2 + 1) * GG + j]);
        Rr[k2] = pack2(r_in[(2 * k2) * GG + 64 + j],   r_in[(2 * k2 + 1) * GG + 64 + j]);
        Rh[k2] = pack2(r_in[(2 * k2) * GG + 128 + j],  r_in[(2 * k2 + 1) * GG + 128 + j]);
    }
    const float brh = bias[GG + 128 + j];   // only h-gate recurrent bias remains

    sm_h[0][u][j] = 0.0f;

    const __half* xpp = g_xp + (size_t)b * SSP * GG;
    // prefetch x-projection for s=0,1 (biases folded at prepass)
    float xz0 = __half2float(xpp[j]);
    float xr0 = __half2float(xpp[64 + j]);
    float xh0 = __half2float(xpp[128 + j]);
    float xz1 = __half2float(xpp[GG + j]);
    float xr1 = __half2float(xpp[GG + 64 + j]);
    float xh1 = __half2float(xpp[GG + 128 + j]);
    __syncthreads();

    for (int s = 0; s < SS; s++) {
        const int p = s & 1;

        // prefetch s+2 (padded rows: no predicate needed)
        const __half* qp = xpp + (size_t)(s + 2) * GG;
        float xz2 = __half2float(qp[j]);
        float xr2 = __half2float(qp[64 + j]);
        float xh2 = __half2float(qp[128 + j]);

        // three recurrent dots, all in-thread (96 fma2, 6 chains of depth 16)
        const ulonglong2* h4 = (const ulonglong2*)sm_h[p][u];   // broadcast LDS.128 (u uniform per warp)
        u64 az0 = 0ull, az1 = 0ull, ar0 = 0ull, ar1 = 0ull, ah0 = 0ull, ah1 = 0ull;
        #pragma unroll
        for (int q2 = 0; q2 < 16; q2++) {
            ulonglong2 hv = h4[q2];
            az0 = fma2(hv.x, Rz[2 * q2],     az0);
            ar0 = fma2(hv.x, Rr[2 * q2],     ar0);
            ah0 = fma2(hv.x, Rh[2 * q2],     ah0);
            az1 = fma2(hv.y, Rz[2 * q2 + 1], az1);
            ar1 = fma2(hv.y, Rr[2 * q2 + 1], ar1);
            ah1 = fma2(hv.y, Rh[2 * q2 + 1], ah1);
        }
        float lo, hi;
        unpack2(add2(az0, az1), lo, hi);  const float az  = xz0 + (lo + hi);
        unpack2(add2(ar0, ar1), lo, hi);  const float ar_ = xr0 + (lo + hi);
        unpack2(add2(ah0, ah1), lo, hi);  const float rh_ = brh + (lo + hi);

        // gates via MUFU.TANH (sigmoid(x) = 0.5 + 0.5*tanh(x/2))
        const float z  = 0.5f + 0.5f * tanh_fast(0.5f * az);
        const float r  = 0.5f + 0.5f * tanh_fast(0.5f * ar_);
        const float hh = tanh_fast(xh0 + r * rh_);
        const float ho = sm_h[p][u][j];
        sm_h[p ^ 1][u][j] = z * (ho - hh) + hh;

        xz0 = xz1; xr0 = xr1; xh0 = xh1;
        xz1 = xz2; xr1 = xr2; xh1 = xh2;
        __syncthreads();   // the ONLY barrier per step
    }

    // final h is in buffer 0 (SS even)
    const float* hf = sm_h[0][u];

    // ---------- delta mean (per batch slot) ----------
    {
        float s = 0.0f;
        const float* dp = inputs + ((size_t)b * SS + (size_t)j * 16) * FIN + 15;
        #pragma unroll
        for (int i = 0; i < 16; i++) s += dp[(size_t)i * FIN];
        sm_r[u][j] = s;
    }
    __syncthreads();
    if (j < 16) sm_r[u][j] += sm_r[u][j + 16] + sm_r[u][j + 32] + sm_r[u][j + 48];
    __syncthreads();
    if (j < 4)  sm_r[u][j] += sm_r[u][j + 4] + sm_r[u][j + 8] + sm_r[u][j + 12];
    __syncthreads();
    const float db = Tp[0] * ((sm_r[u][0] + sm_r[u][1]) + (sm_r[u][2] + sm_r[u][3])) * (1.0f / (float)SS);

    // ---------- Epilogue: MLP head + BN ----------
    {
        float acc = b1[j];
        #pragma unroll 8
        for (int k = 0; k < HH; k++)
            acc += (hf[k] + db) * w1[k * HH + j];
        float hr = fmaxf(acc, 0.0f);
        float hb = (hr - bn_mean[j]) * rsqrtf(bn_var[j] + 1e-3f) * bn_gamma[j] + bn_beta[j];
        sm_e[u][j] = hb * w2[j];
    }
    __syncthreads();

    if (j == 0) {
        float acc = b2[0];
        #pragma unroll 8
        for (int k = 0; k < HH; k++) acc += sm_e[u][k];
        out[b] = acc;
    }
}

extern "C" void kernel_launch(void* const* d_in, const int* in_sizes, int n_in,
                              void* d_out, int out_size) {
    const float* inputs   = (const float*)d_in[0];
    const float* gk       = (const float*)d_in[1];
    const float* grk      = (const float*)d_in[2];
    const float* gbias    = (const float*)d_in[3];
    const float* w1       = (const float*)d_in[4];
    const float* b1       = (const float*)d_in[5];
    const float* bn_gamma = (const float*)d_in[6];
    const float* bn_beta  = (const float*)d_in[7];
    const float* bn_mean  = (const float*)d_in[8];
    const float* bn_var   = (const float*)d_in[9];
    const float* w2       = (const float*)d_in[10];
    const float* b2       = (const float*)d_in[11];
    const float* T        = (const float*)d_in[12];
    float* out = (float*)d_out;

    xproj_kernel<<<(BB * SS) / XROWS, NTP>>>(inputs, gk, gbias);
    gru_scan_kernel<<<BB / NBC, NBC * HH>>>(inputs, grk, gbias, w1, b1,
                                            bn_gamma, bn_beta, bn_mean, bn_var,
                                            w2, b2, T, out);
}

// round 11
// speedup vs baseline: 1.0377x; 1.0377x over previous
#include <cuda_runtime.h>
#include <cuda_bf16.h>
#include <cuda_fp16.h>

// Problem constants
#define BB   512
#define SS   1024
#define SSP  (SS + 2)  // padded rows per batch (prefetch overrun)
#define FIN  16        // features per (b,s); feature 15 is delta
#define HH   64
#define GG   192       // 3*H
#define NBC  2         // batches per scan CTA (warps 0,1 -> u0; 2,3 -> u1)
#define XROWS 64       // rows per x-projection block
#define NTP  192       // x-projection block threads

typedef unsigned long long u64;

// Device scratch (sanctioned alternative to cudaMalloc)
__device__ __half g_xp[(size_t)BB * SSP * GG];   // x-projection + folded biases (fp16, ~202 MB)

// ---- packed f32x2 helpers (bit-exact fp32, 2 FMA per fma-pipe slot) ----
__device__ __forceinline__ u64 pack2(float lo, float hi) {
    u64 r; asm("mov.b64 %0, {%1, %2};" : "=l"(r) : "f"(lo), "f"(hi)); return r;
}
__device__ __forceinline__ void unpack2(u64 v, float& lo, float& hi) {
    asm("mov.b64 {%0, %1}, %2;" : "=f"(lo), "=f"(hi) : "l"(v));
}
__device__ __forceinline__ u64 fma2(u64 a, u64 b, u64 c) {
    u64 d; asm("fma.rn.f32x2 %0, %1, %2, %3;" : "=l"(d) : "l"(a), "l"(b), "l"(c)); return d;
}
__device__ __forceinline__ u64 add2(u64 a, u64 b) {
    u64 d; asm("add.rn.f32x2 %0, %1, %2;" : "=l"(d) : "l"(a), "l"(b)); return d;
}
__device__ __forceinline__ float tanh_fast(float x) {
    float t; asm("tanh.approx.f32 %0, %1;" : "=f"(t) : "f"(x)); return t;
}
// Named barrier: syncs only the 64 threads of one batch-half (ids 1 and 2).
__device__ __forceinline__ void bar_half(int u) {
    asm volatile("bar.sync %0, 64;" :: "r"(u + 1) : "memory");
}

// ---------------- Kernel 1: x-projection pre-pass (fp16 out, biases folded) ----------------
// For g<128 (z,r gates): xp = x.K + b_in[g] + b_rec[g]
// For g>=128 (h gate):   xp = x.K + b_in[g]            (b_rec stays in scan)
__global__ __launch_bounds__(NTP)
void xproj_kernel(const float* __restrict__ inputs,
                  const float* __restrict__ k_in,
                  const float* __restrict__ bias) {
    __shared__ __align__(16) float sx[XROWS * FIN];
    const int g  = threadIdx.x;
    const int bb = blockIdx.x / (SS / XROWS);        // batch
    const int s0 = (blockIdx.x % (SS / XROWS)) * XROWS;
    const size_t row0 = (size_t)bb * SS + s0;        // source row
    const size_t drow0 = (size_t)bb * SSP + s0;      // dest row (padded layout)

    u64 K2[8];
    #pragma unroll
    for (int f2 = 0; f2 < 8; f2++) {
        float lo = k_in[(2 * f2) * GG + g];
        float hi = (2 * f2 + 1 < 15) ? k_in[(2 * f2 + 1) * GG + g] : 0.0f;
        K2[f2] = pack2(lo, hi);
    }
    const float bfold = bias[g] + ((g < 128) ? bias[GG + g] : 0.0f);

    const float4* src = (const float4*)(inputs + row0 * FIN);
    for (int i = g; i < XROWS * 4; i += NTP) ((float4*)sx)[i] = src[i];
    __syncthreads();

    __half* dst = g_xp + drow0 * GG + g;
    #pragma unroll 4
    for (int r = 0; r < XROWS; r++) {
        const ulonglong2* xr = (const ulonglong2*)(sx + r * FIN);
        ulonglong2 xv0 = xr[0], xv1 = xr[1];
        u64 c0 = fma2(xv0.x, K2[0], 0ull);
        u64 c1 = fma2(xv0.y, K2[1], 0ull);
        c0 = fma2(xv1.x, K2[2], c0);
        c1 = fma2(xv1.y, K2[3], c1);
        ulonglong2 xv2 = xr[2], xv3 = xr[3];
        c0 = fma2(xv2.x, K2[4], c0);
        c1 = fma2(xv2.y, K2[5], c1);
        c0 = fma2(xv3.x, K2[6], c0);
        c1 = fma2(xv3.y, K2[7], c1);
        float lo, hi; unpack2(add2(c0, c1), lo, hi);
        dst[(size_t)r * GG] = __float2half(bfold + (lo + hi));
    }
}

// ---------------- Kernel 2: GRU scan — 2 independent batch-halves per CTA ----------------
// Threads 0-63 (warps 0,1) own batch u=0; threads 64-127 (warps 2,3) own u=1.
// The halves never synchronize with each other: each uses its own named barrier.
// This populates all 4 SMSPs while keeping 4 independent sync domains per SM.
__global__ __launch_bounds__(NBC * HH, 2)
void gru_scan_kernel(const float* __restrict__ inputs,   // (B,S,16) - for delta mean
                     const float* __restrict__ r_in,     // (64,192)
                     const float* __restrict__ bias,     // (2,192)
                     const float* __restrict__ w1,       // (64,64)
                     const float* __restrict__ b1,       // (64)
                     const float* __restrict__ bn_gamma,
                     const float* __restrict__ bn_beta,
                     const float* __restrict__ bn_mean,
                     const float* __restrict__ bn_var,
                     const float* __restrict__ w2,       // (64,1)
                     const float* __restrict__ b2,       // (1)
                     const float* __restrict__ Tp,       // (1)
                     float* __restrict__ out)            // (B,1)
{
    __shared__ __align__(16) float sm_h[NBC][2][HH];   // per-half double-buffered hidden state
    __shared__ float sm_e[NBC][HH];
    __shared__ float sm_r[NBC][HH];

    const int tid = threadIdx.x;
    const int j = tid & 63;               // column triple 0..63
    const int u = tid >> 6;               // batch half (warp-uniform)
    const int b = blockIdx.x * NBC + u;   // batch

    // Recurrent weights for columns j (z), 64+j (r), 128+j (h); f32x2 pairs over k
    u64 Rz[32], Rr[32], Rh[32];
    #pragma unroll
    for (int k2 = 0; k2 < 32; k2++) {
        Rz[k2] = pack2(r_in[(2 * k2) * GG + j],        r_in[(2 * k2 + 1) * GG + j]);
        Rr[k2] = pack2(r_in[(2 * k2) * GG + 64 + j],   r_in[(2 * k2 + 1) * GG + 64 + j]);
        Rh[k2] = pack2(r_in[(2 * k2) * GG + 128 + j],  r_in[(2 * k2 + 1) * GG + 128 + j]);
    }
    const float brh = bias[GG + 128 + j];   // only h-gate recurrent bias remains

    sm_h[u][0][j] = 0.0f;

    const __half* xpp = g_xp + (size_t)b * SSP * GG;
    // prefetch x-projection for s=0,1 (biases folded at prepass)
    float xz0 = __half2float(xpp[j]);
    float xr0 = __half2float(xpp[64 + j]);
    float xh0 = __half2float(xpp[128 + j]);
    float xz1 = __half2float(xpp[GG + j]);
    float xr1 = __half2float(xpp[GG + 64 + j]);
    float xh1 = __half2float(xpp[GG + 128 + j]);
    bar_half(u);

    for (int s = 0; s < SS; s++) {
        const int p = s & 1;

        // prefetch s+2 (padded rows: no predicate needed)
        const __half* qp = xpp + (size_t)(s + 2) * GG;
        float xz2 = __half2float(qp[j]);
        float xr2 = __half2float(qp[64 + j]);
        float xh2 = __half2float(qp[128 + j]);

        // three recurrent dots, all in-thread (96 fma2, 6 chains of depth 16)
        const ulonglong2* h4 = (const ulonglong2*)sm_h[u][p];   // broadcast LDS.128
        u64 az0 = 0ull, az1 = 0ull, ar0 = 0ull, ar1 = 0ull, ah0 = 0ull, ah1 = 0ull;
        #pragma unroll
        for (int q2 = 0; q2 < 16; q2++) {
            ulonglong2 hv = h4[q2];
            az0 = fma2(hv.x, Rz[2 * q2],     az0);
            ar0 = fma2(hv.x, Rr[2 * q2],     ar0);
            ah0 = fma2(hv.x, Rh[2 * q2],     ah0);
            az1 = fma2(hv.y, Rz[2 * q2 + 1], az1);
            ar1 = fma2(hv.y, Rr[2 * q2 + 1], ar1);
            ah1 = fma2(hv.y, Rh[2 * q2 + 1], ah1);
        }
        float lo, hi;
        unpack2(add2(az0, az1), lo, hi);  const float az  = xz0 + (lo + hi);
        unpack2(add2(ar0, ar1), lo, hi);  const float ar_ = xr0 + (lo + hi);
        unpack2(add2(ah0, ah1), lo, hi);  const float rh_ = brh + (lo + hi);

        // gates via MUFU.TANH (sigmoid(x) = 0.5 + 0.5*tanh(x/2))
        const float z  = 0.5f + 0.5f * tanh_fast(0.5f * az);
        const float r  = 0.5f + 0.5f * tanh_fast(0.5f * ar_);
        const float hh = tanh_fast(xh0 + r * rh_);
        const float ho = sm_h[u][p][j];
        sm_h[u][p ^ 1][j] = z * (ho - hh) + hh;

        xz0 = xz1; xr0 = xr1; xh0 = xh1;
        xz1 = xz2; xr1 = xr2; xh1 = xh2;
        bar_half(u);   // syncs ONLY this batch's 64 threads
    }

    // final h is in buffer 0 (SS even)
    const float* hf = sm_h[u][0];

    // ---------- delta mean (per batch half) ----------
    {
        float s = 0.0f;
        const float* dp = inputs + ((size_t)b * SS + (size_t)j * 16) * FIN + 15;
        #pragma unroll
        for (int i = 0; i < 16; i++) s += dp[(size_t)i * FIN];
        sm_r[u][j] = s;
    }
    bar_half(u);
    if (j < 16) sm_r[u][j] += sm_r[u][j + 16] + sm_r[u][j + 32] + sm_r[u][j + 48];
    bar_half(u);
    if (j < 4)  sm_r[u][j] += sm_r[u][j + 4] + sm_r[u][j + 8] + sm_r[u][j + 12];
    bar_half(u);
    const float db = Tp[0] * ((sm_r[u][0] + sm_r[u][1]) + (sm_r[u][2] + sm_r[u][3])) * (1.0f / (float)SS);

    // ---------- Epilogue: MLP head + BN ----------
    {
        float acc = b1[j];
        #pragma unroll 8
        for (int k = 0; k < HH; k++)
            acc += (hf[k] + db) * w1[k * HH + j];
        float hr = fmaxf(acc, 0.0f);
        float hb = (hr - bn_mean[j]) * rsqrtf(bn_var[j] + 1e-3f) * bn_gamma[j] + bn_beta[j];
        sm_e[u][j] = hb * w2[j];
    }
    bar_half(u);

    if (j == 0) {
        float acc = b2[0];
        #pragma unroll 8
        for (int k = 0; k < HH; k++) acc += sm_e[u][k];
        out[b] = acc;
    }
}

extern "C" void kernel_launch(void* const* d_in, const int* in_sizes, int n_in,
                              void* d_out, int out_size) {
    const float* inputs   = (const float*)d_in[0];
    const float* gk       = (const float*)d_in[1];
    const float* grk      = (const float*)d_in[2];
    const float* gbias    = (const float*)d_in[3];
    const float* w1       = (const float*)d_in[4];
    const float* b1       = (const float*)d_in[5];
    const float* bn_gamma = (const float*)d_in[6];
    const float* bn_beta  = (const float*)d_in[7];
    const float* bn_mean  = (const float*)d_in[8];
    const float* bn_var   = (const float*)d_in[9];
    const float* w2       = (const float*)d_in[10];
    const float* b2       = (const float*)d_in[11];
    const float* T        = (const float*)d_in[12];
    float* out = (float*)d_out;

    xproj_kernel<<<(BB * SS) / XROWS, NTP>>>(inputs, gk, gbias);
    gru_scan_kernel<<<BB / NBC, NBC * HH>>>(inputs, grk, gbias, w1, b1,
                                            bn_gamma, bn_beta, bn_mean, bn_var,
                                            w2, b2, T, out);
}

// round 12
// speedup vs baseline: 1.2562x; 1.2105x over previous
#include <cuda_runtime.h>
#include <cuda_bf16.h>
#include <cuda_fp16.h>

// Problem constants
#define BB   512
#define SS   1024
#define SSP  (SS + 2)  // padded rows per batch (prefetch overrun)
#define FIN  16        // features per (b,s); feature 15 is delta
#define HH   64
#define GG   192       // 3*H
#define NBC  2         // batches per scan CTA
#define NT   256       // 8 warps; warps 0-3 = batch 0, warps 4-7 = batch 1
#define XROWS 64       // rows per x-projection block
#define NTP  192       // x-projection block threads

typedef unsigned long long u64;

// Device scratch (sanctioned alternative to cudaMalloc)
__device__ __half g_xp[(size_t)BB * SSP * GG];   // x-projection + folded biases (fp16, ~202 MB)

// ---- packed f32x2 helpers (bit-exact fp32, 2 FMA per fma-pipe slot) ----
__device__ __forceinline__ u64 pack2(float lo, float hi) {
    u64 r; asm("mov.b64 %0, {%1, %2};" : "=l"(r) : "f"(lo), "f"(hi)); return r;
}
__device__ __forceinline__ void unpack2(u64 v, float& lo, float& hi) {
    asm("mov.b64 {%0, %1}, %2;" : "=f"(lo), "=f"(hi) : "l"(v));
}
__device__ __forceinline__ u64 fma2(u64 a, u64 b, u64 c) {
    u64 d; asm("fma.rn.f32x2 %0, %1, %2, %3;" : "=l"(d) : "l"(a), "l"(b), "l"(c)); return d;
}
__device__ __forceinline__ u64 add2(u64 a, u64 b) {
    u64 d; asm("add.rn.f32x2 %0, %1, %2;" : "=l"(d) : "l"(a), "l"(b)); return d;
}
__device__ __forceinline__ float tanh_fast(float x) {
    float t; asm("tanh.approx.f32 %0, %1;" : "=f"(t) : "f"(x)); return t;
}
// Named barrier: syncs only the 128 threads (4 warps) of one batch.
__device__ __forceinline__ void bar_batch(int bt) {
    asm volatile("bar.sync %0, 128;" :: "r"(bt + 1) : "memory");
}

// ---------------- Kernel 1: x-projection pre-pass (fp16 out, biases folded) ----------------
__global__ __launch_bounds__(NTP)
void xproj_kernel(const float* __restrict__ inputs,
                  const float* __restrict__ k_in,
                  const float* __restrict__ bias) {
    __shared__ __align__(16) float sx[XROWS * FIN];
    const int g  = threadIdx.x;
    const int bb = blockIdx.x / (SS / XROWS);
    const int s0 = (blockIdx.x % (SS / XROWS)) * XROWS;
    const size_t row0 = (size_t)bb * SS + s0;
    const size_t drow0 = (size_t)bb * SSP + s0;

    u64 K2[8];
    #pragma unroll
    for (int f2 = 0; f2 < 8; f2++) {
        float lo = k_in[(2 * f2) * GG + g];
        float hi = (2 * f2 + 1 < 15) ? k_in[(2 * f2 + 1) * GG + g] : 0.0f;
        K2[f2] = pack2(lo, hi);
    }
    const float bfold = bias[g] + ((g < 128) ? bias[GG + g] : 0.0f);

    const float4* src = (const float4*)(inputs + row0 * FIN);
    for (int i = g; i < XROWS * 4; i += NTP) ((float4*)sx)[i] = src[i];
    __syncthreads();

    __half* dst = g_xp + drow0 * GG + g;
    #pragma unroll 4
    for (int r = 0; r < XROWS; r++) {
        const ulonglong2* xr = (const ulonglong2*)(sx + r * FIN);
        ulonglong2 xv0 = xr[0], xv1 = xr[1];
        u64 c0 = fma2(xv0.x, K2[0], 0ull);
        u64 c1 = fma2(xv0.y, K2[1], 0ull);
        c0 = fma2(xv1.x, K2[2], c0);
        c1 = fma2(xv1.y, K2[3], c1);
        ulonglong2 xv2 = xr[2], xv3 = xr[3];
        c0 = fma2(xv2.x, K2[4], c0);
        c1 = fma2(xv2.y, K2[5], c1);
        c0 = fma2(xv3.x, K2[6], c0);
        c1 = fma2(xv3.y, K2[7], c1);
        float lo, hi; unpack2(add2(c0, c1), lo, hi);
        dst[(size_t)r * GG] = __float2half(bfold + (lo + hi));
    }
}

// ---------------- Kernel 2: GRU scan — k-split, 2 batches/CTA, 4 warps/batch ----------------
// Thread = (j, k-half). Warp w4 covers j in [16*w4, 16*w4+16); lanes 0-15 = k-half 0,
// lanes 16-31 = k-half 1. Partner for the cross-half reduction is lane^16 (same j).
// Per-batch named barrier keeps the two batch domains of a CTA independent.
__global__ __launch_bounds__(NT, 2)
void gru_scan_kernel(const float* __restrict__ inputs,   // (B,S,16) - for delta mean
                     const float* __restrict__ r_in,     // (64,192)
                     const float* __restrict__ bias,     // (2,192)
                     const float* __restrict__ w1,       // (64,64)
                     const float* __restrict__ b1,       // (64)
                     const float* __restrict__ bn_gamma,
                     const float* __restrict__ bn_beta,
                     const float* __restrict__ bn_mean,
                     const float* __restrict__ bn_var,
                     const float* __restrict__ w2,       // (64,1)
                     const float* __restrict__ b2,       // (1)
                     const float* __restrict__ Tp,       // (1)
                     float* __restrict__ out)            // (B,1)
{
    __shared__ __align__(16) float sm_h[NBC][2][HH];   // per-batch double-buffered hidden state
    __shared__ float sm_e[NBC][HH];
    __shared__ float sm_r[NBC][128];

    const int tid  = threadIdx.x;
    const int bt   = tid >> 7;              // batch slot (warp-uniform: warps 0-3 / 4-7)
    const int t    = tid & 127;             // thread within batch
    const int lane = tid & 31;
    const int w4   = (tid >> 5) & 3;        // warp within batch
    const int jj   = w4 * 16 + (lane & 15); // owned column triple 0..63
    const int kh   = lane >> 4;             // k-half: 0 -> k in [0,32), 1 -> [32,64)
    const int b    = blockIdx.x * NBC + bt; // batch

    // Recurrent weights for columns jj (z), 64+jj (r), 128+jj (h), k-half only
    u64 Rz[16], Rr[16], Rh[16];
    #pragma unroll
    for (int t2 = 0; t2 < 16; t2++) {
        const int k = 32 * kh + 2 * t2;
        Rz[t2] = pack2(r_in[k * GG + jj],        r_in[(k + 1) * GG + jj]);
        Rr[t2] = pack2(r_in[k * GG + 64 + jj],   r_in[(k + 1) * GG + 64 + jj]);
        Rh[t2] = pack2(r_in[k * GG + 128 + jj],  r_in[(k + 1) * GG + 128 + jj]);
    }
    const float brh = bias[GG + 128 + jj];   // only h-gate recurrent bias remains

    if (t < HH) sm_h[bt][0][t] = 0.0f;

    const __half* xpp = g_xp + (size_t)b * SSP * GG;
    // prefetch x-projection for s=0,1 (biases folded at prepass)
    float xz0 = __half2float(xpp[jj]);
    float xr0 = __half2float(xpp[64 + jj]);
    float xh0 = __half2float(xpp[128 + jj]);
    float xz1 = __half2float(xpp[GG + jj]);
    float xr1 = __half2float(xpp[GG + 64 + jj]);
    float xh1 = __half2float(xpp[GG + 128 + jj]);
    bar_batch(bt);

    for (int s = 0; s < SS; s++) {
        const int p = s & 1;

        // prefetch s+2 (padded rows: no predicate needed)
        const __half* qp = xpp + (size_t)(s + 2) * GG;
        float xz2 = __half2float(qp[jj]);
        float xr2 = __half2float(qp[64 + jj]);
        float xh2 = __half2float(qp[128 + jj]);

        // three recurrent half-dots (48 fma2; 6 chains of depth 8)
        const ulonglong2* h4 = (const ulonglong2*)(&sm_h[bt][p][32 * kh]);
        u64 az0 = 0ull, az1 = 0ull, ar0 = 0ull, ar1 = 0ull, ah0 = 0ull, ah1 = 0ull;
        #pragma unroll
        for (int q2 = 0; q2 < 8; q2++) {
            ulonglong2 hv = h4[q2];
            az0 = fma2(hv.x, Rz[2 * q2],     az0);
            ar0 = fma2(hv.x, Rr[2 * q2],     ar0);
            ah0 = fma2(hv.x, Rh[2 * q2],     ah0);
            az1 = fma2(hv.y, Rz[2 * q2 + 1], az1);
            ar1 = fma2(hv.y, Rr[2 * q2 + 1], ar1);
            ah1 = fma2(hv.y, Rh[2 * q2 + 1], ah1);
        }
        float lo, hi;
        unpack2(add2(az0, az1), lo, hi);  float sz = lo + hi;
        unpack2(add2(ar0, ar1), lo, hi);  float sr = lo + hi;
        unpack2(add2(ah0, ah1), lo, hi);  float sh = lo + hi;

        // cross-half reduction: partner lane^16 owns the other 32 k's of the same jj
        sz += __shfl_xor_sync(0xffffffffu, sz, 16);
        sr += __shfl_xor_sync(0xffffffffu, sr, 16);
        sh += __shfl_xor_sync(0xffffffffu, sh, 16);

        // gates (computed redundantly in both halves; MUFU.TANH path)
        const float z  = 0.5f + 0.5f * tanh_fast(0.5f * (xz0 + sz));
        const float r  = 0.5f + 0.5f * tanh_fast(0.5f * (xr0 + sr));
        const float hh = tanh_fast(xh0 + r * (brh + sh));
        const float ho = sm_h[bt][p][jj];
        if (kh == 0) sm_h[bt][p ^ 1][jj] = z * (ho - hh) + hh;

        xz0 = xz1; xr0 = xr1; xh0 = xh1;
        xz1 = xz2; xr1 = xr2; xh1 = xh2;
        bar_batch(bt);   // syncs ONLY this batch's 128 threads
    }

    // final h is in buffer 0 (SS even)
    const float* hf = sm_h[bt][0];

    // ---------- delta mean (per batch; 128 threads x 8 elements) ----------
    {
        float sacc = 0.0f;
        #pragma unroll
        for (int i = 0; i < 8; i++)
            sacc += inputs[((size_t)b * SS + (size_t)(i * 128 + t)) * FIN + 15];
        sm_r[bt][t] = sacc;
    }
    bar_batch(bt);
    if (t < 32) sm_r[bt][t] += sm_r[bt][t + 32] + sm_r[bt][t + 64] + sm_r[bt][t + 96];
    bar_batch(bt);
    if (t < 8)  sm_r[bt][t] += sm_r[bt][t + 8] + sm_r[bt][t + 16] + sm_r[bt][t + 24];
    bar_batch(bt);
    const float db = Tp[0] *
        (((sm_r[bt][0] + sm_r[bt][1]) + (sm_r[bt][2] + sm_r[bt][3])) +
         ((sm_r[bt][4] + sm_r[bt][5]) + (sm_r[bt][6] + sm_r[bt][7]))) * (1.0f / (float)SS);

    // ---------- Epilogue: MLP head + BN (k-half 0 threads own the 64 columns) ----------
    if (kh == 0) {
        float acc = b1[jj];
        #pragma unroll 8
        for (int k = 0; k < HH; k++)
            acc += (hf[k] + db) * w1[k * HH + jj];
        float hr = fmaxf(acc, 0.0f);
        float hb = (hr - bn_mean[jj]) * rsqrtf(bn_var[jj] + 1e-3f) * bn_gamma[jj] + bn_beta[jj];
        sm_e[bt][jj] = hb * w2[jj];
    }
    bar_batch(bt);

    if (t == 0) {
        float acc = b2[0];
        #pragma unroll 8
        for (int k = 0; k < HH; k++) acc += sm_e[bt][k];
        out[b] = acc;
    }
}

extern "C" void kernel_launch(void* const* d_in, const int* in_sizes, int n_in,
                              void* d_out, int out_size) {
    const float* inputs   = (const float*)d_in[0];
    const float* gk       = (const float*)d_in[1];
    const float* grk      = (const float*)d_in[2];
    const float* gbias    = (const float*)d_in[3];
    const float* w1       = (const float*)d_in[4];
    const float* b1       = (const float*)d_in[5];
    const float* bn_gamma = (const float*)d_in[6];
    const float* bn_beta  = (const float*)d_in[7];
    const float* bn_mean  = (const float*)d_in[8];
    const float* bn_var   = (const float*)d_in[9];
    const float* w2       = (const float*)d_in[10];
    const float* b2       = (const float*)d_in[11];
    const float* T        = (const float*)d_in[12];
    float* out = (float*)d_out;

    xproj_kernel<<<(BB * SS) / XROWS, NTP>>>(inputs, gk, gbias);
    gru_scan_kernel<<<BB / NBC, NT>>>(inputs, grk, gbias, w1, b1,
                                      bn_gamma, bn_beta, bn_mean, bn_var,
                                      w2, b2, T, out);
}